// round 7
// baseline (speedup 1.0000x reference)
#include <cuda_runtime.h>
#include <cuda_bf16.h>
#include <cstdint>

// AggregationLayer: y[s] = mean over edges e with segment_ids[e]==s of
//                   layer_values[gather_idx[e], :]
// d_in[0]: layer_values f32 [N_SRC*64]
// d_in[1]: gather_idx   i32 [E]
// d_in[2]: segment_ids  i32 [E] (sorted ascending)
// out: f32 [n_seg*64]

#define D 64

// CSR row offsets scratch (n_seg <= 1M supported). +1 terminator.
__device__ int g_begin[1048577];

// Vectorized boundary finder: 4 edges per thread via int4.
__global__ void __launch_bounds__(256)
build_csr_kernel(const int* __restrict__ segs, int E, int n_seg)
{
    const int e4 = (blockIdx.x * blockDim.x + threadIdx.x) * 4;
    if (e4 >= E) return;

    int s0, s1, s2, s3;
    const int rem = E - e4;
    if (rem >= 4) {
        int4 v = *reinterpret_cast<const int4*>(segs + e4);
        s0 = v.x; s1 = v.y; s2 = v.z; s3 = v.w;
    } else {
        s0 = __ldg(segs + e4);
        s1 = (rem > 1) ? __ldg(segs + e4 + 1) : s0;
        s2 = (rem > 2) ? __ldg(segs + e4 + 2) : s1;
        s3 = s2;
    }

    int prev = (e4 == 0) ? -1 : __ldg(segs + e4 - 1);

    int cur[4] = {s0, s1, s2, s3};
    const int kmax = (rem < 4) ? rem : 4;
    #pragma unroll
    for (int k = 0; k < 4; ++k) {
        if (k < kmax) {
            for (int t = prev + 1; t <= cur[k]; ++t) g_begin[t] = e4 + k;
            prev = cur[k];
        }
    }
    if (e4 + kmax >= E) {
        for (int t = prev + 1; t <= n_seg; ++t) g_begin[t] = E;
    }
}

// Warp per segment; half-warp per row (float4 per lane -> one LDG.128 loads 2 rows).
__global__ void __launch_bounds__(256)
agg_seg_mean_kernel(const float* __restrict__ vals,
                    const int*   __restrict__ gidx,
                    float*       __restrict__ out,
                    int n_seg)
{
    const int warp_id = (blockIdx.x * blockDim.x + threadIdx.x) >> 5;
    const int lane    = threadIdx.x & 31;
    if (warp_id >= n_seg) return;
    const int s = warp_id;

    const int begin = __ldg(&g_begin[s]);
    const int end   = __ldg(&g_begin[s + 1]);

    const float4* __restrict__ vals4 = reinterpret_cast<const float4*>(vals);
    const int half = lane >> 4;     // 0 or 1: which row of the pair
    const int sub  = lane & 15;     // column group (4 floats each)

    float ax = 0.f, ay = 0.f, az = 0.f, aw = 0.f;

    for (int base = begin; base < end; base += 32) {
        const int n = min(32, end - base);
        int myidx = 0;
        if (lane < n) myidx = __ldg(gidx + base + lane);

        const int npairs = n >> 1;
        int p = 0;
        // 4 pairs unrolled = 8 rows in flight per warp
        for (; p + 4 <= npairs; p += 4) {
            int r0 = __shfl_sync(0xffffffffu, myidx, 2*(p+0) + half);
            int r1 = __shfl_sync(0xffffffffu, myidx, 2*(p+1) + half);
            int r2 = __shfl_sync(0xffffffffu, myidx, 2*(p+2) + half);
            int r3 = __shfl_sync(0xffffffffu, myidx, 2*(p+3) + half);
            float4 v0 = __ldg(vals4 + (size_t)r0 * (D/4) + sub);
            float4 v1 = __ldg(vals4 + (size_t)r1 * (D/4) + sub);
            float4 v2 = __ldg(vals4 + (size_t)r2 * (D/4) + sub);
            float4 v3 = __ldg(vals4 + (size_t)r3 * (D/4) + sub);
            ax += v0.x + v1.x + v2.x + v3.x;
            ay += v0.y + v1.y + v2.y + v3.y;
            az += v0.z + v1.z + v2.z + v3.z;
            aw += v0.w + v1.w + v2.w + v3.w;
        }
        for (; p < npairs; ++p) {
            int r = __shfl_sync(0xffffffffu, myidx, 2*p + half);
            float4 v = __ldg(vals4 + (size_t)r * (D/4) + sub);
            ax += v.x; ay += v.y; az += v.z; aw += v.w;
        }
        if (n & 1) {
            int r = __shfl_sync(0xffffffffu, myidx, n - 1);
            if (half == 0) {
                float4 v = __ldg(vals4 + (size_t)r * (D/4) + sub);
                ax += v.x; ay += v.y; az += v.z; aw += v.w;
            }
        }
    }

    // combine the two half-warp partials (lanes l and l+16 hold same columns)
    ax += __shfl_xor_sync(0xffffffffu, ax, 16);
    ay += __shfl_xor_sync(0xffffffffu, ay, 16);
    az += __shfl_xor_sync(0xffffffffu, az, 16);
    aw += __shfl_xor_sync(0xffffffffu, aw, 16);

    const int cnt = end - begin;
    const float inv = 1.0f / (float)max(cnt, 1);
    if (half == 0) {
        float4 res;
        res.x = ax * inv; res.y = ay * inv; res.z = az * inv; res.w = aw * inv;
        reinterpret_cast<float4*>(out)[(size_t)s * (D/4) + sub] = res;
    }
}

extern "C" void kernel_launch(void* const* d_in, const int* in_sizes, int n_in,
                              void* d_out, int out_size)
{
    const float* vals = (const float*)d_in[0];
    const int*   gidx = (const int*)d_in[1];
    const int*   segs = (const int*)d_in[2];
    float*       out  = (float*)d_out;

    const int E     = in_sizes[1];
    const int n_seg = out_size / D;

    // 1) build CSR offsets (4 edges/thread)
    {
        const int threads = 256;
        const int elems_per_block = threads * 4;
        const int blocks = (E + elems_per_block - 1) / elems_per_block;
        build_csr_kernel<<<blocks, threads>>>(segs, E, n_seg);
    }
    // 2) warp-per-segment gather + mean
    {
        const int threads = 256;            // 8 warps/block
        const int wpb = threads / 32;
        const int blocks = (n_seg + wpb - 1) / wpb;
        agg_seg_mean_kernel<<<blocks, threads>>>(vals, gidx, out, n_seg);
    }
}

// round 8
// speedup vs baseline: 1.1720x; 1.1720x over previous
#include <cuda_runtime.h>
#include <cuda_bf16.h>
#include <cstdint>

// AggregationLayer: y[s] = mean over edges e with segment_ids[e]==s of
//                   layer_values[gather_idx[e], :]
// d_in[0]: layer_values f32 [N_SRC*64]
// d_in[1]: gather_idx   i32 [E]
// d_in[2]: segment_ids  i32 [E] (sorted ascending)
// out: f32 [n_seg*64]

#define D 64
#define SEGS_PER_BLOCK 8
#define IDX_CAP 1024

// CSR row offsets scratch (n_seg <= 1M supported). +1 terminator.
__device__ int g_begin[1048577];

// Vectorized boundary finder: 4 edges per thread via int4.
__global__ void __launch_bounds__(256)
build_csr_kernel(const int* __restrict__ segs, int E, int n_seg)
{
    const int e4 = (blockIdx.x * blockDim.x + threadIdx.x) * 4;
    if (e4 >= E) return;

    int s0, s1, s2, s3;
    const int rem = E - e4;
    if (rem >= 4) {
        int4 v = *reinterpret_cast<const int4*>(segs + e4);
        s0 = v.x; s1 = v.y; s2 = v.z; s3 = v.w;
    } else {
        s0 = __ldg(segs + e4);
        s1 = (rem > 1) ? __ldg(segs + e4 + 1) : s0;
        s2 = (rem > 2) ? __ldg(segs + e4 + 2) : s1;
        s3 = s2;
    }

    int prev = (e4 == 0) ? -1 : __ldg(segs + e4 - 1);

    int cur[4] = {s0, s1, s2, s3};
    const int kmax = (rem < 4) ? rem : 4;
    #pragma unroll
    for (int k = 0; k < 4; ++k) {
        if (k < kmax) {
            for (int t = prev + 1; t <= cur[k]; ++t) g_begin[t] = e4 + k;
            prev = cur[k];
        }
    }
    if (e4 + kmax >= E) {
        for (int t = prev + 1; t <= n_seg; ++t) g_begin[t] = E;
    }
}

// Block handles 8 consecutive segments. Cooperative smem staging of the
// CSR offsets + the block's whole edge-index span, then warp-per-segment
// row gathering with 8 independent row loads in flight.
__global__ void __launch_bounds__(256)
agg_seg_mean_kernel(const float* __restrict__ vals,
                    const int*   __restrict__ gidx,
                    float*       __restrict__ out,
                    int n_seg)
{
    __shared__ int s_begin[SEGS_PER_BLOCK + 1];
    __shared__ int s_idx[IDX_CAP];

    const int tid = threadIdx.x;
    const int b0  = blockIdx.x * SEGS_PER_BLOCK;

    if (tid <= SEGS_PER_BLOCK) {
        int s = b0 + tid;
        if (s > n_seg) s = n_seg;
        s_begin[tid] = g_begin[s];
    }
    __syncthreads();

    const int base0 = s_begin[0];
    const int span  = s_begin[SEGS_PER_BLOCK] - base0;
    const bool cached = (span <= IDX_CAP);

    if (cached) {
        for (int i = tid; i < span; i += 256)
            s_idx[i] = __ldg(gidx + base0 + i);
    }
    __syncthreads();

    const int w    = tid >> 5;
    const int lane = tid & 31;
    const int s    = b0 + w;
    if (s >= n_seg) return;

    const int begin = s_begin[w];
    const int end   = s_begin[w + 1];

    const float2* __restrict__ vals2 = reinterpret_cast<const float2*>(vals);

    float ax = 0.f, ay = 0.f;

    if (cached) {
        int j = begin - base0;
        const int jend = end - base0;
        // 8 independent 256B row loads in flight per warp
        for (; j + 8 <= jend; j += 8) {
            int r0 = s_idx[j + 0];
            int r1 = s_idx[j + 1];
            int r2 = s_idx[j + 2];
            int r3 = s_idx[j + 3];
            int r4 = s_idx[j + 4];
            int r5 = s_idx[j + 5];
            int r6 = s_idx[j + 6];
            int r7 = s_idx[j + 7];
            float2 v0 = __ldg(vals2 + (size_t)r0 * (D/2) + lane);
            float2 v1 = __ldg(vals2 + (size_t)r1 * (D/2) + lane);
            float2 v2 = __ldg(vals2 + (size_t)r2 * (D/2) + lane);
            float2 v3 = __ldg(vals2 + (size_t)r3 * (D/2) + lane);
            float2 v4 = __ldg(vals2 + (size_t)r4 * (D/2) + lane);
            float2 v5 = __ldg(vals2 + (size_t)r5 * (D/2) + lane);
            float2 v6 = __ldg(vals2 + (size_t)r6 * (D/2) + lane);
            float2 v7 = __ldg(vals2 + (size_t)r7 * (D/2) + lane);
            ax += v0.x + v1.x + v2.x + v3.x;
            ay += v0.y + v1.y + v2.y + v3.y;
            ax += v4.x + v5.x + v6.x + v7.x;
            ay += v4.y + v5.y + v6.y + v7.y;
        }
        for (; j < jend; ++j) {
            int r = s_idx[j];
            float2 v = __ldg(vals2 + (size_t)r * (D/2) + lane);
            ax += v.x;
            ay += v.y;
        }
    } else {
        // rare fallback: block's edge span exceeded the smem cache
        int e = begin;
        for (; e + 4 <= end; e += 4) {
            int r0 = __ldg(gidx + e + 0);
            int r1 = __ldg(gidx + e + 1);
            int r2 = __ldg(gidx + e + 2);
            int r3 = __ldg(gidx + e + 3);
            float2 v0 = __ldg(vals2 + (size_t)r0 * (D/2) + lane);
            float2 v1 = __ldg(vals2 + (size_t)r1 * (D/2) + lane);
            float2 v2 = __ldg(vals2 + (size_t)r2 * (D/2) + lane);
            float2 v3 = __ldg(vals2 + (size_t)r3 * (D/2) + lane);
            ax += v0.x + v1.x + v2.x + v3.x;
            ay += v0.y + v1.y + v2.y + v3.y;
        }
        for (; e < end; ++e) {
            int r = __ldg(gidx + e);
            float2 v = __ldg(vals2 + (size_t)r * (D/2) + lane);
            ax += v.x;
            ay += v.y;
        }
    }

    const int cnt = end - begin;
    const float inv = 1.0f / (float)max(cnt, 1);
    float2 res;
    res.x = ax * inv;
    res.y = ay * inv;
    reinterpret_cast<float2*>(out)[(size_t)s * (D/2) + lane] = res;
}

extern "C" void kernel_launch(void* const* d_in, const int* in_sizes, int n_in,
                              void* d_out, int out_size)
{
    const float* vals = (const float*)d_in[0];
    const int*   gidx = (const int*)d_in[1];
    const int*   segs = (const int*)d_in[2];
    float*       out  = (float*)d_out;

    const int E     = in_sizes[1];
    const int n_seg = out_size / D;

    // 1) build CSR offsets (4 edges/thread)
    {
        const int threads = 256;
        const int elems_per_block = threads * 4;
        const int blocks = (E + elems_per_block - 1) / elems_per_block;
        build_csr_kernel<<<blocks, threads>>>(segs, E, n_seg);
    }
    // 2) block-staged warp-per-segment gather + mean
    {
        const int threads = 256;
        const int blocks = (n_seg + SEGS_PER_BLOCK - 1) / SEGS_PER_BLOCK;
        agg_seg_mean_kernel<<<blocks, threads>>>(vals, gidx, out, n_seg);
    }
}

// round 9
// speedup vs baseline: 1.2107x; 1.0331x over previous
#include <cuda_runtime.h>
#include <cuda_bf16.h>
#include <cstdint>

// AggregationLayer: y[s] = mean over edges e with segment_ids[e]==s of
//                   layer_values[gather_idx[e], :]
// d_in[0]: layer_values f32 [N_SRC*64]
// d_in[1]: gather_idx   i32 [E]
// d_in[2]: segment_ids  i32 [E] (sorted ascending)
// out: f32 [n_seg*64]

#define D 64
#define SEGS_PER_BLOCK 32
#define SEGS_PER_WARP 4
#define IDX_CAP 2048

// CSR row offsets scratch (n_seg <= 1M supported). +1 terminator.
__device__ int g_begin[1048577];

// Vectorized boundary finder: 4 edges per thread via int4.
__global__ void __launch_bounds__(256)
build_csr_kernel(const int* __restrict__ segs, int E, int n_seg)
{
    const int e4 = (blockIdx.x * blockDim.x + threadIdx.x) * 4;
    if (e4 >= E) return;

    int s0, s1, s2, s3;
    const int rem = E - e4;
    if (rem >= 4) {
        int4 v = *reinterpret_cast<const int4*>(segs + e4);
        s0 = v.x; s1 = v.y; s2 = v.z; s3 = v.w;
    } else {
        s0 = __ldg(segs + e4);
        s1 = (rem > 1) ? __ldg(segs + e4 + 1) : s0;
        s2 = (rem > 2) ? __ldg(segs + e4 + 2) : s1;
        s3 = s2;
    }

    int prev = (e4 == 0) ? -1 : __ldg(segs + e4 - 1);

    int cur[4] = {s0, s1, s2, s3};
    const int kmax = (rem < 4) ? rem : 4;
    #pragma unroll
    for (int k = 0; k < 4; ++k) {
        if (k < kmax) {
            for (int t = prev + 1; t <= cur[k]; ++t) g_begin[t] = e4 + k;
            prev = cur[k];
        }
    }
    if (e4 + kmax >= E) {
        for (int t = prev + 1; t <= n_seg; ++t) g_begin[t] = E;
    }
}

// Block handles 32 consecutive segments (4 per warp). One coalesced smem
// staging of offsets + the block's full edge-index span amortized over a
// 4x longer row-load phase.
__global__ void __launch_bounds__(256)
agg_seg_mean_kernel(const float* __restrict__ vals,
                    const int*   __restrict__ gidx,
                    float*       __restrict__ out,
                    int n_seg)
{
    __shared__ int s_begin[SEGS_PER_BLOCK + 1];
    __shared__ int s_idx[IDX_CAP];

    const int tid = threadIdx.x;
    const int b0  = blockIdx.x * SEGS_PER_BLOCK;

    if (tid <= SEGS_PER_BLOCK) {
        int s = b0 + tid;
        if (s > n_seg) s = n_seg;
        s_begin[tid] = g_begin[s];
    }
    __syncthreads();

    const int base0 = s_begin[0];
    const int span  = s_begin[SEGS_PER_BLOCK] - base0;
    const bool cached = (span <= IDX_CAP);

    if (cached) {
        for (int i = tid; i < span; i += 256)
            s_idx[i] = __ldg(gidx + base0 + i);
    }
    __syncthreads();

    const int w    = tid >> 5;
    const int lane = tid & 31;

    const float2* __restrict__ vals2 = reinterpret_cast<const float2*>(vals);

    #pragma unroll
    for (int ss = 0; ss < SEGS_PER_WARP; ++ss) {
        const int sl = w * SEGS_PER_WARP + ss;   // local segment index
        const int s  = b0 + sl;
        if (s >= n_seg) break;

        const int begin = s_begin[sl];
        const int end   = s_begin[sl + 1];

        float ax = 0.f, ay = 0.f;

        if (cached) {
            int j = begin - base0;
            const int jend = end - base0;
            for (; j + 8 <= jend; j += 8) {
                int r0 = s_idx[j + 0];
                int r1 = s_idx[j + 1];
                int r2 = s_idx[j + 2];
                int r3 = s_idx[j + 3];
                int r4 = s_idx[j + 4];
                int r5 = s_idx[j + 5];
                int r6 = s_idx[j + 6];
                int r7 = s_idx[j + 7];
                float2 v0 = __ldg(vals2 + (size_t)r0 * (D/2) + lane);
                float2 v1 = __ldg(vals2 + (size_t)r1 * (D/2) + lane);
                float2 v2 = __ldg(vals2 + (size_t)r2 * (D/2) + lane);
                float2 v3 = __ldg(vals2 + (size_t)r3 * (D/2) + lane);
                float2 v4 = __ldg(vals2 + (size_t)r4 * (D/2) + lane);
                float2 v5 = __ldg(vals2 + (size_t)r5 * (D/2) + lane);
                float2 v6 = __ldg(vals2 + (size_t)r6 * (D/2) + lane);
                float2 v7 = __ldg(vals2 + (size_t)r7 * (D/2) + lane);
                ax += v0.x + v1.x + v2.x + v3.x;
                ay += v0.y + v1.y + v2.y + v3.y;
                ax += v4.x + v5.x + v6.x + v7.x;
                ay += v4.y + v5.y + v6.y + v7.y;
            }
            for (; j < jend; ++j) {
                int r = s_idx[j];
                float2 v = __ldg(vals2 + (size_t)r * (D/2) + lane);
                ax += v.x;
                ay += v.y;
            }
        } else {
            // rare fallback: block's edge span exceeded the smem cache
            int e = begin;
            for (; e + 4 <= end; e += 4) {
                int r0 = __ldg(gidx + e + 0);
                int r1 = __ldg(gidx + e + 1);
                int r2 = __ldg(gidx + e + 2);
                int r3 = __ldg(gidx + e + 3);
                float2 v0 = __ldg(vals2 + (size_t)r0 * (D/2) + lane);
                float2 v1 = __ldg(vals2 + (size_t)r1 * (D/2) + lane);
                float2 v2 = __ldg(vals2 + (size_t)r2 * (D/2) + lane);
                float2 v3 = __ldg(vals2 + (size_t)r3 * (D/2) + lane);
                ax += v0.x + v1.x + v2.x + v3.x;
                ay += v0.y + v1.y + v2.y + v3.y;
            }
            for (; e < end; ++e) {
                int r = __ldg(gidx + e);
                float2 v = __ldg(vals2 + (size_t)r * (D/2) + lane);
                ax += v.x;
                ay += v.y;
            }
        }

        const int cnt = end - begin;
        const float inv = 1.0f / (float)max(cnt, 1);
        float2 res;
        res.x = ax * inv;
        res.y = ay * inv;
        reinterpret_cast<float2*>(out)[(size_t)s * (D/2) + lane] = res;
    }
}

extern "C" void kernel_launch(void* const* d_in, const int* in_sizes, int n_in,
                              void* d_out, int out_size)
{
    const float* vals = (const float*)d_in[0];
    const int*   gidx = (const int*)d_in[1];
    const int*   segs = (const int*)d_in[2];
    float*       out  = (float*)d_out;

    const int E     = in_sizes[1];
    const int n_seg = out_size / D;

    // 1) build CSR offsets (4 edges/thread)
    {
        const int threads = 256;
        const int elems_per_block = threads * 4;
        const int blocks = (E + elems_per_block - 1) / elems_per_block;
        build_csr_kernel<<<blocks, threads>>>(segs, E, n_seg);
    }
    // 2) block-staged (32 segs) warp-per-segment gather + mean
    {
        const int threads = 256;
        const int blocks = (n_seg + SEGS_PER_BLOCK - 1) / SEGS_PER_BLOCK;
        agg_seg_mean_kernel<<<blocks, threads>>>(vals, gidx, out, n_seg);
    }
}

// round 10
// speedup vs baseline: 1.2560x; 1.0374x over previous
#include <cuda_runtime.h>
#include <cuda_bf16.h>
#include <cstdint>

// AggregationLayer: y[s] = mean over edges e with segment_ids[e]==s of
//                   layer_values[gather_idx[e], :]
// d_in[0]: layer_values f32 [N_SRC*64]
// d_in[1]: gather_idx   i32 [E]
// d_in[2]: segment_ids  i32 [E] (sorted ascending)
// out: f32 [n_seg*64]

#define D 64
#define SEGS_PER_BLOCK 32
#define SEGS_PER_WARP 4
#define IDX_CAP 2048

// CSR row offsets scratch (n_seg <= 1M supported). +1 terminator.
__device__ int g_begin[1048577];

// Vectorized boundary finder: 4 edges per thread via int4.
__global__ void __launch_bounds__(256)
build_csr_kernel(const int* __restrict__ segs, int E, int n_seg)
{
    const int e4 = (blockIdx.x * blockDim.x + threadIdx.x) * 4;
    if (e4 >= E) return;

    int s0, s1, s2, s3;
    const int rem = E - e4;
    if (rem >= 4) {
        int4 v = *reinterpret_cast<const int4*>(segs + e4);
        s0 = v.x; s1 = v.y; s2 = v.z; s3 = v.w;
    } else {
        s0 = __ldg(segs + e4);
        s1 = (rem > 1) ? __ldg(segs + e4 + 1) : s0;
        s2 = (rem > 2) ? __ldg(segs + e4 + 2) : s1;
        s3 = s2;
    }

    int prev = (e4 == 0) ? -1 : __ldg(segs + e4 - 1);

    int cur[4] = {s0, s1, s2, s3};
    const int kmax = (rem < 4) ? rem : 4;
    #pragma unroll
    for (int k = 0; k < 4; ++k) {
        if (k < kmax) {
            for (int t = prev + 1; t <= cur[k]; ++t) g_begin[t] = e4 + k;
            prev = cur[k];
        }
    }
    if (e4 + kmax >= E) {
        for (int t = prev + 1; t <= n_seg; ++t) g_begin[t] = E;
    }
}

// Block handles 32 consecutive segments (4 per warp). One coalesced smem
// staging of offsets + the block's full edge-index span. Row-load phase uses
// predicated full-width 8-bursts: no serialized remainder loads.
__global__ void __launch_bounds__(256)
agg_seg_mean_kernel(const float* __restrict__ vals,
                    const int*   __restrict__ gidx,
                    float*       __restrict__ out,
                    int n_seg)
{
    __shared__ int s_begin[SEGS_PER_BLOCK + 1];
    __shared__ int s_idx[IDX_CAP];

    const int tid = threadIdx.x;
    const int b0  = blockIdx.x * SEGS_PER_BLOCK;

    if (tid <= SEGS_PER_BLOCK) {
        int s = b0 + tid;
        if (s > n_seg) s = n_seg;
        s_begin[tid] = g_begin[s];
    }
    __syncthreads();

    const int base0 = s_begin[0];
    const int span  = s_begin[SEGS_PER_BLOCK] - base0;
    const bool cached = (span <= IDX_CAP);

    if (cached) {
        for (int i = tid; i < span; i += 256)
            s_idx[i] = __ldg(gidx + base0 + i);
    }
    __syncthreads();

    const int w    = tid >> 5;
    const int lane = tid & 31;

    const float2* __restrict__ vals2 = reinterpret_cast<const float2*>(vals);

    #pragma unroll
    for (int ss = 0; ss < SEGS_PER_WARP; ++ss) {
        const int sl = w * SEGS_PER_WARP + ss;   // local segment index
        const int s  = b0 + sl;
        if (s >= n_seg) break;

        const int begin = s_begin[sl];
        const int end   = s_begin[sl + 1];
        const int cnt   = end - begin;

        float ax = 0.f, ay = 0.f;

        if (cached) {
            const int j0   = begin - base0;
            const int jend = end - base0;
            // predicated full-width bursts: every iteration issues 8
            // independent loads; out-of-range slots re-load edge j0
            // (L1 hit) with weight 0.
            for (int j = j0; j < jend; j += 8) {
                #pragma unroll
                for (int k = 0; k < 8; ++k) {
                    const int  jj = j + k;
                    const bool ok = (jj < jend);
                    const int  r  = s_idx[ok ? jj : j0];
                    const float w8 = ok ? 1.0f : 0.0f;
                    float2 v = __ldg(vals2 + (size_t)r * (D/2) + lane);
                    ax = fmaf(w8, v.x, ax);
                    ay = fmaf(w8, v.y, ay);
                }
            }
        } else {
            // rare fallback: block's edge span exceeded the smem cache
            for (int e = begin; e < end; e += 8) {
                #pragma unroll
                for (int k = 0; k < 8; ++k) {
                    const int  ee = e + k;
                    const bool ok = (ee < end);
                    const int  r  = __ldg(gidx + (ok ? ee : begin));
                    const float w8 = ok ? 1.0f : 0.0f;
                    float2 v = __ldg(vals2 + (size_t)r * (D/2) + lane);
                    ax = fmaf(w8, v.x, ax);
                    ay = fmaf(w8, v.y, ay);
                }
            }
        }

        const float inv = 1.0f / (float)max(cnt, 1);
        float2 res;
        res.x = ax * inv;
        res.y = ay * inv;
        reinterpret_cast<float2*>(out)[(size_t)s * (D/2) + lane] = res;
    }
}

extern "C" void kernel_launch(void* const* d_in, const int* in_sizes, int n_in,
                              void* d_out, int out_size)
{
    const float* vals = (const float*)d_in[0];
    const int*   gidx = (const int*)d_in[1];
    const int*   segs = (const int*)d_in[2];
    float*       out  = (float*)d_out;

    const int E     = in_sizes[1];
    const int n_seg = out_size / D;

    // 1) build CSR offsets (4 edges/thread)
    {
        const int threads = 256;
        const int elems_per_block = threads * 4;
        const int blocks = (E + elems_per_block - 1) / elems_per_block;
        build_csr_kernel<<<blocks, threads>>>(segs, E, n_seg);
    }
    // 2) block-staged (32 segs) warp-per-segment gather + mean
    {
        const int threads = 256;
        const int blocks = (n_seg + SEGS_PER_BLOCK - 1) / SEGS_PER_BLOCK;
        agg_seg_mean_kernel<<<blocks, threads>>>(vals, gidx, out, n_seg);
    }
}